// round 3
// baseline (speedup 1.0000x reference)
#include <cuda_runtime.h>

// Problem constants
#define BB    64
#define FSPEC 128
#define TT    128
#define NPOS  16384
#define NNEG  16384
#define TFEA  128
#define DD    64

typedef unsigned long long ull;

// Scratch
__device__ float g_A[BB * DD * TT];          // 2 MB   A[b][d][t]
__device__ float g_PN[(NPOS + NNEG) * DD];   // 8 MB   PN[row][d]
__device__ int4  g_chunks[320];              // pos work units {seg,row0,nrows,_}
__device__ int   g_nPos;

__device__ __forceinline__ ull fma2(ull a, ull b, ull c) {
    ull d;
    asm("fma.rn.f32x2 %0, %1, %2, %3;" : "=l"(d) : "l"(a), "l"(b), "l"(c));
    return d;
}
__device__ __forceinline__ ull dup2(float v) {
    ull r;
    asm("mov.b64 %0, {%1, %1};" : "=l"(r) : "f"(v));
    return r;
}

// ---------------------------------------------------------------------------
// kAP:
//   blocks [0,512)   : kP  — 64-row tiles, PN[row] = X[row] @ Wt^T
//   blocks [512,768) : kA  — A[b] = Wa @ spec[b], 64d x 32t tiles
//   block  768       : scheduler — build single-segment 64-row chunks of pos
// ---------------------------------------------------------------------------
__global__ void __launch_bounds__(256) kAP(
    const float* __restrict__ spec, const float* __restrict__ pos,
    const float* __restrict__ neg,  const float* __restrict__ Wa,
    const float* __restrict__ Wt,   const int* __restrict__ pos_seg)
{
    extern __shared__ float sm[];
    const int tid = threadIdx.x;
    const int blk = blockIdx.x;

    if (blk < 512) {
        // ---------------- kP: text projection, 64 rows/block ----------------
        float* sX   = sm;                 // [64][132]
        float* sWtT = sm + 64 * 132;      // [128 k][68 c]

        const int rowbase = blk * 64;
        const float4* X = (const float4*)((rowbase < NPOS)
                            ? (pos + (size_t)rowbase * TFEA)
                            : (neg + (size_t)(rowbase - NPOS) * TFEA));

        // stage X [64][128] (float4, row stride 132 keeps 16B alignment)
        for (int i = tid; i < 64 * 32; i += 256) {
            int r = i >> 5, c = i & 31;
            *(float4*)&sX[r * 132 + 4 * c] = X[i];
        }
        // stage Wt transposed: sWtT[k][c] = Wt[c*128 + k]
        for (int i = tid; i < DD * TFEA; i += 256) {
            int c = i >> 7, k = i & 127;
            sWtT[k * 68 + c] = Wt[i];
        }
        __syncthreads();

        const int lane = tid & 31, w = tid >> 5;
        const int tx = lane & 7, rg = lane >> 3;
        const int r0 = w * 8 + rg * 2;           // 2 rows per thread

        ull acc[2][2][2];                        // [row][chunk][pair]
#pragma unroll
        for (int r = 0; r < 2; r++)
#pragma unroll
            for (int j = 0; j < 2; j++) { acc[r][j][0] = 0; acc[r][j][1] = 0; }

#pragma unroll 8
        for (int k = 0; k < TFEA; k++) {
            ull x0 = dup2(sX[r0 * 132 + k]);
            ull x1 = dup2(sX[(r0 + 1) * 132 + k]);
#pragma unroll
            for (int j = 0; j < 2; j++) {
                ulonglong2 a = *(const ulonglong2*)&sWtT[k * 68 + 4 * (tx + 8 * j)];
                acc[0][j][0] = fma2(x0, a.x, acc[0][j][0]);
                acc[0][j][1] = fma2(x0, a.y, acc[0][j][1]);
                acc[1][j][0] = fma2(x1, a.x, acc[1][j][0]);
                acc[1][j][1] = fma2(x1, a.y, acc[1][j][1]);
            }
        }

#pragma unroll
        for (int r = 0; r < 2; r++)
#pragma unroll
            for (int j = 0; j < 2; j++) {
                ulonglong2 o; o.x = acc[r][j][0]; o.y = acc[r][j][1];
                *(ulonglong2*)&g_PN[(size_t)(rowbase + r0 + r) * DD + 4 * (tx + 8 * j)] = o;
            }
    } else if (blk < 768) {
        // ---------------- kA: audio projection ----------------
        float* sWa = sm;                  // [64][129]
        float* sSp = sm + 64 * 129;       // [128][36]

        const int ab = blk - 512;
        const int b  = ab >> 2;
        const int tq = ab & 3;

        for (int i = tid; i < DD * FSPEC; i += 256)
            sWa[(i >> 7) * 129 + (i & 127)] = Wa[i];
        const float* sp = spec + (size_t)b * FSPEC * TT + tq * 32;
        for (int i = tid; i < FSPEC * 32; i += 256) {
            int k = i >> 5, c = i & 31;
            sSp[k * 36 + c] = sp[k * TT + c];
        }
        __syncthreads();

        const int tx = tid & 15, ty = tid >> 4;
        const int d0 = ty * 4, t0 = tx * 2;

        ull acc[4] = {0, 0, 0, 0};
#pragma unroll 8
        for (int k = 0; k < FSPEC; k++) {
            ull bp = *(const ull*)&sSp[k * 36 + t0];
#pragma unroll
            for (int i = 0; i < 4; i++)
                acc[i] = fma2(dup2(sWa[(d0 + i) * 129 + k]), bp, acc[i]);
        }
#pragma unroll
        for (int i = 0; i < 4; i++)
            *(ull*)&g_A[(size_t)(b * DD + d0 + i) * TT + tq * 32 + t0] = acc[i];
    } else {
        // ---------------- scheduler: single-segment chunks ----------------
        __shared__ int segStart[65];
        if (tid < 64) {
            int s = tid, lo = 0, hi = NPOS;
            while (lo < hi) {
                int mid = (lo + hi) >> 1;
                if (pos_seg[mid] < s) lo = mid + 1; else hi = mid;
            }
            segStart[s] = lo;
        }
        if (tid == 0) segStart[64] = NPOS;
        __syncthreads();
        if (tid == 0) {
            int idx = 0;
            for (int s = 0; s < 64; s++) {
                int st = segStart[s], en = segStart[s + 1];
                for (int r = st; r < en; r += 64) {
                    int nr = en - r; if (nr > 64) nr = 64;
                    g_chunks[idx] = make_int4(s, r, nr, 0);
                    idx++;
                }
            }
            g_nPos = idx;
        }
    }
}

// ---------------------------------------------------------------------------
// kQA: out[row] = PN[row] @ A[seg]    (64-row single-segment blocks)
//   blocks [0,320)   : pos chunks (early-exit past g_nPos)
//   blocks [320,576) : neg chunks (seg = row0>>8, aligned -> single segment)
// warp: 8 tx x 4 row-groups; thread: 2 rows x 16 t (4 x LDS.128, conflict-free)
// ---------------------------------------------------------------------------
__global__ void __launch_bounds__(256, 3) kQA(float* __restrict__ out) {
    extern __shared__ float sm[];
    float* sA = sm;              // [64 k][132 t]
    float* sP = sm + 64 * 132;   // [64 r][68 k]

    const int tid = threadIdx.x;
    const int blk = blockIdx.x;

    int seg, row0, nrows, pnRow;
    float* outp;
    if (blk < 320) {
        if (blk >= g_nPos) return;
        int4 ch = g_chunks[blk];
        seg = ch.x; row0 = ch.y; nrows = ch.z;
        pnRow = row0;
        outp = out + (size_t)row0 * TT;
    } else {
        int c = blk - 320;
        row0 = c * 64; seg = row0 >> 8; nrows = 64;
        pnRow = NPOS + row0;
        outp = out + (size_t)(NPOS + row0) * TT;
    }

    // stage A[seg] (64x128) and P rows (64x64), both float4
    const float4* Ag = (const float4*)(g_A + (size_t)seg * DD * TT);
    for (int i = tid; i < 2048; i += 256) {
        int k = i >> 5, c = i & 31;
        *(float4*)&sA[k * 132 + 4 * c] = Ag[i];
    }
    const float4* Pg = (const float4*)(g_PN + (size_t)pnRow * DD);
    for (int i = tid; i < 1024; i += 256) {
        int r = i >> 4, c = i & 15;
        int rr = r < nrows ? r : nrows - 1;      // clamp; masked at store
        *(float4*)&sP[r * 68 + 4 * c] = Pg[rr * 16 + c];
    }
    __syncthreads();

    const int lane = tid & 31, w = tid >> 5;
    const int tx = lane & 7, rg = lane >> 3;
    const int r0 = w * 8 + rg * 2;               // 2 rows per thread

    ull acc[2][4][2];
#pragma unroll
    for (int r = 0; r < 2; r++)
#pragma unroll
        for (int j = 0; j < 4; j++) { acc[r][j][0] = 0; acc[r][j][1] = 0; }

#pragma unroll 8
    for (int k = 0; k < DD; k++) {
        ull p0 = dup2(sP[r0 * 68 + k]);
        ull p1 = dup2(sP[(r0 + 1) * 68 + k]);
#pragma unroll
        for (int j = 0; j < 4; j++) {
            // 8 tx lanes read 8 contiguous 16B chunks -> 128B, conflict-free
            ulonglong2 a = *(const ulonglong2*)&sA[k * 132 + 4 * (tx + 8 * j)];
            acc[0][j][0] = fma2(p0, a.x, acc[0][j][0]);
            acc[0][j][1] = fma2(p0, a.y, acc[0][j][1]);
            acc[1][j][0] = fma2(p1, a.x, acc[1][j][0]);
            acc[1][j][1] = fma2(p1, a.y, acc[1][j][1]);
        }
    }

#pragma unroll
    for (int r = 0; r < 2; r++) {
        if (r0 + r < nrows) {
            float* dst = outp + (size_t)(r0 + r) * TT;
#pragma unroll
            for (int j = 0; j < 4; j++) {
                ulonglong2 o; o.x = acc[r][j][0]; o.y = acc[r][j][1];
                *(ulonglong2*)&dst[4 * (tx + 8 * j)] = o;
            }
        }
    }
}

// ---------------------------------------------------------------------------
extern "C" void kernel_launch(void* const* d_in, const int* in_sizes, int n_in,
                              void* d_out, int out_size) {
    const float* spec    = (const float*)d_in[0];
    const float* pos     = (const float*)d_in[1];
    const float* neg     = (const float*)d_in[2];
    const int*   pos_seg = (const int*)  d_in[3];
    const float* Wa      = (const float*)d_in[4];
    const float* Wt      = (const float*)d_in[5];
    float* out = (float*)d_out;

    const int smemAP = (64 * 132 + 128 * 68) * 4;   // 68,608
    const int smemQA = (64 * 132 + 64 * 68) * 4;    // 51,200

    cudaFuncSetAttribute(kAP, cudaFuncAttributeMaxDynamicSharedMemorySize, smemAP);
    cudaFuncSetAttribute(kQA, cudaFuncAttributeMaxDynamicSharedMemorySize, smemQA);

    kAP<<<769, 256, smemAP>>>(spec, pos, neg, Wa, Wt, pos_seg);
    kQA<<<576, 256, smemQA>>>(out);
}